// round 6
// baseline (speedup 1.0000x reference)
#include <cuda_runtime.h>

// SlidingMean, 2-kernel split:
//  K1: vertical 79-tap sliding sum, thread = column, 32 rows/thread carried,
//      no smem / no barriers. colsum -> device global (L2-resident).
//  K2: warp-per-row horizontal 69-tap window via register prefix scan
//      (+ swizzled smem taps) fused with normalize epilogue. No block barriers.

#define HH 512
#define WW 512
#define NB 32
#define KH 79
#define KW 69
#define RH 39   // (KH-1)/2
#define RW 34   // (KW-1)/2
#define RPT 32  // rows per thread in K1

__device__ float g_colsum[(size_t)NB * HH * WW];

// ---------------------------------------------------------------------------
// K1: vertical sliding sum. Grid = NB * (HH/RPT) * (WW/256) = 32*16*2 = 1024
// blocks of 256 threads. Warp reads fully coalesced along W.
// ---------------------------------------------------------------------------
__global__ __launch_bounds__(256) void vert_sum_kernel(const float* __restrict__ x) {
    const int blk = blockIdx.x;
    const int wc  = blk & 1;           // column half
    const int hc  = (blk >> 1) & 15;   // 16 row-chunks of 32
    const int n   = blk >> 5;          // batch
    const int col = wc * 256 + threadIdx.x;
    const int h0  = hc * RPT;

    const float* __restrict__ xp = x + (size_t)n * HH * WW + col;
    float* __restrict__ cp = g_colsum + ((size_t)n * HH + h0) * WW + col;

    const bool interior = (h0 - RH >= 0) && (h0 + RPT - 1 + RH + 1 <= HH - 1);

    float s;
    if (interior) {
        float s0 = 0.f, s1 = 0.f, s2 = 0.f, s3 = 0.f;
        const float* p = xp + (size_t)(h0 - RH) * WW;
        #pragma unroll
        for (int r = 0; r < 76; r += 4) {
            s0 += p[(size_t)(r + 0) * WW];
            s1 += p[(size_t)(r + 1) * WW];
            s2 += p[(size_t)(r + 2) * WW];
            s3 += p[(size_t)(r + 3) * WW];
        }
        s = (s0 + s1) + (s2 + s3)
          + p[(size_t)76 * WW] + p[(size_t)77 * WW] + p[(size_t)78 * WW];

        const float* __restrict__ pa = xp + (size_t)(h0 + RH + 1) * WW;
        const float* __restrict__ pb = xp + (size_t)(h0 - RH) * WW;
        #pragma unroll 8
        for (int k = 0; k < RPT; ++k) {
            cp[(size_t)k * WW] = s;
            s += pa[(size_t)k * WW] - pb[(size_t)k * WW];
        }
    } else {
        s = 0.f;
        int lo = h0 - RH; if (lo < 0) lo = 0;
        int hi = h0 + RH; if (hi > HH - 1) hi = HH - 1;
        for (int r = lo; r <= hi; ++r) s += xp[(size_t)r * WW];
        #pragma unroll 8
        for (int k = 0; k < RPT; ++k) {
            cp[(size_t)k * WW] = s;
            int add = h0 + k + RH + 1;
            int sub = h0 + k - RH;
            float a = (add < HH) ? xp[(size_t)add * WW] : 0.f;
            float b = (sub >= 0) ? xp[(size_t)sub * WW] : 0.f;
            s += a - b;
        }
    }
}

// XOR swizzle on 16B units within a 2KB row (conflict-free for float4 blocked
// stores and near-conflict-free scalar tap loads).
__device__ __forceinline__ int swz(int e) {
    int u = e >> 2;
    int pu = u ^ ((u >> 3) & 7);
    return (pu << 2) | (e & 3);
}

// ---------------------------------------------------------------------------
// K2: warp-per-row horizontal window + epilogue. Grid = NB*HH/16 = 1024 blocks
// of 512 threads (16 independent warps, each owns one row + 2KB smem).
// No __syncthreads anywhere.
// ---------------------------------------------------------------------------
__global__ __launch_bounds__(512, 4) void horiz_norm_kernel(const float* __restrict__ x,
                                                            float* __restrict__ out) {
    __shared__ float sP[16 * WW];      // 32 KB, one 2KB row per warp

    const int t = threadIdx.x;
    const int lane = t & 31;
    const int wrp  = t >> 5;
    const int rowid = blockIdx.x * 16 + wrp;          // 0 .. NB*HH-1
    const size_t rbase = (size_t)rowid * WW;

    const float* __restrict__ crow = g_colsum + rbase;
    float* __restrict__ row = sP + (wrp << 9);
    const unsigned FULL = 0xffffffffu;

    // load 16 contiguous colsum elements per lane (blocked) via 4 x LDG.128
    float p[16];
    const float4* __restrict__ c4 = reinterpret_cast<const float4*>(crow);
    #pragma unroll
    for (int c = 0; c < 4; ++c) {
        float4 v = __ldg(&c4[(lane << 2) + c]);
        p[c * 4 + 0] = v.x; p[c * 4 + 1] = v.y; p[c * 4 + 2] = v.z; p[c * 4 + 3] = v.w;
    }
    // local inclusive prefix + warp scan of totals
    #pragma unroll
    for (int j = 1; j < 16; ++j) p[j] += p[j - 1];
    float tot = p[15];
    float inc = tot;
    #pragma unroll
    for (int off = 1; off < 32; off <<= 1) {
        float u = __shfl_up_sync(FULL, inc, off);
        if (lane >= off) inc += u;
    }
    float excl = inc - tot;
    #pragma unroll
    for (int j = 0; j < 16; ++j) p[j] += excl;
    // store prefix to this warp's smem row (swizzled float4)
    #pragma unroll
    for (int c = 0; c < 4; ++c) {
        int u = (lane << 2) + c;
        int pu = u ^ ((u >> 3) & 7);
        *reinterpret_cast<float4*>(row + (pu << 2)) =
            make_float4(p[c * 4 + 0], p[c * 4 + 1], p[c * 4 + 2], p[c * 4 + 3]);
    }
    __syncwarp();   // warp-private row

    // windowed diff + normalize, cyclic mapping (coalesced x/out)
    const float inv_cnt = 1.0f / (float)(KH * KW);
    const float inv_std = 0.2f;  // 1/5
    #pragma unroll
    for (int i = 0; i < 16; ++i) {
        int w = lane + (i << 5);
        int hiI = w + RW; if (hiI > WW - 1) hiI = WW - 1;
        int loI = w - RW - 1;
        float hi = row[swz(hiI)];
        float lo = (loI >= 0) ? row[swz(loI)] : 0.0f;
        float winsum = hi - lo;
        size_t o = rbase + w;
        out[o] = (x[o] - winsum * inv_cnt) * inv_std;
    }
}

extern "C" void kernel_launch(void* const* d_in, const int* in_sizes, int n_in,
                              void* d_out, int out_size) {
    const float* x = (const float*)d_in[0];
    float* out = (float*)d_out;

    vert_sum_kernel<<<NB * (HH / RPT) * (WW / 256), 256>>>(x);
    horiz_norm_kernel<<<NB * HH / 16, 512>>>(x, out);
}

// round 7
// speedup vs baseline: 1.4949x; 1.4949x over previous
#include <cuda_runtime.h>

// SlidingMean: out = (x - boxfilter_79x69(x)) / 5, SAME (zero) padding.
//  K1: S8[n][g][c] = sum of 8 consecutive rows (tiny 4MB intermediate, L2-hot;
//      also warms L2 with x).
//  K2: fused kernel (R3 structure): vertical 79-tap window init from S8 taps
//      (+ edge rows) -> sliding fill into swizzled smem -> per-warp register
//      prefix scan -> windowed diff + normalize.

#define HH 512
#define WW 512
#define NB 32
#define KH 79
#define KW 69
#define RH 39   // (KH-1)/2
#define RW 34   // (KW-1)/2
#define TH 16   // output rows per block in K2 (1 row per warp in phase B)
#define NG 64   // 8-row groups per image

__device__ float g_s8[(size_t)NB * NG * WW];   // 4 MB

// ---------------------------------------------------------------------------
// K1: 8-row group sums. Grid = NB*NG blocks of 512 threads (thread = column).
// ---------------------------------------------------------------------------
__global__ __launch_bounds__(512) void s8_kernel(const float* __restrict__ x) {
    const int blk = blockIdx.x;            // n*NG + g
    const int g = blk & (NG - 1);
    const int n = blk >> 6;
    const int c = threadIdx.x;

    const float* __restrict__ p = x + ((size_t)n * HH + (size_t)g * 8) * WW + c;
    float a0 = p[0]          + p[(size_t)1 * WW];
    float a1 = p[(size_t)2 * WW] + p[(size_t)3 * WW];
    float a2 = p[(size_t)4 * WW] + p[(size_t)5 * WW];
    float a3 = p[(size_t)6 * WW] + p[(size_t)7 * WW];
    g_s8[((size_t)blk << 9) + c] = (a0 + a1) + (a2 + a3);
}

// XOR swizzle on 16B units within a 2KB row: conflict-free for scalar stores
// at consecutive elements, float4 loads at unit 4*lane, and scalar tap loads
// at consecutive elements.
__device__ __forceinline__ int swz(int e) {
    int u = e >> 2;
    int pu = u ^ ((u >> 3) & 7);
    return (pu << 2) | (e & 3);
}

__global__ __launch_bounds__(512, 4) void sliding_mean_fused(const float* __restrict__ x,
                                                             float* __restrict__ out) {
    __shared__ float smemC[TH * WW];   // 32 KB (swizzled colsums -> prefixes)

    const int blk = blockIdx.x;
    const int hc = blk & 31;           // 32 h-chunks of 16 rows
    const int n  = blk >> 5;           // batch
    const int h0 = hc * TH;
    const int t  = threadIdx.x;        // column index in phase A
    const int lane = t & 31;
    const int wrp  = t >> 5;

    const size_t gbase = (size_t)n * HH * WW;
    const float* __restrict__ xp = x + gbase + t;
    const float* __restrict__ s8p = g_s8 + ((size_t)n * NG << 9) + t;
    const int st = swz(t);

    // ---- init: window sum over rows [h0-RH, h0+RH] clamped, via S8 taps ----
    int lo = h0 - RH; if (lo < 0) lo = 0;
    int hi = h0 + RH; if (hi > HH - 1) hi = HH - 1;
    const int glo = (lo + 7) >> 3;
    const int ghi = (hi + 1) >> 3;

    float s0 = 0.f, s1 = 0.f;
    for (int r = lo; r < (glo << 3); ++r) s0 += xp[(size_t)r * WW];
    int g = glo;
    for (; g + 1 < ghi; g += 2) {
        s0 += s8p[(size_t)g << 9];
        s1 += s8p[(size_t)(g + 1) << 9];
    }
    if (g < ghi) s0 += s8p[(size_t)g << 9];
    for (int r = (ghi << 3); r <= hi; ++r) s1 += xp[(size_t)r * WW];
    float s = s0 + s1;

    // ---- phase A: sliding fill of 16 colsum rows into swizzled smem ---------
    const bool interior = (h0 - RH >= 0) && (h0 + TH - 1 + RH + 1 <= HH - 1);
    if (interior) {
        const float* __restrict__ pa = xp + (size_t)(h0 + RH + 1) * WW;
        const float* __restrict__ pb = xp + (size_t)(h0 - RH) * WW;
        #pragma unroll
        for (int k = 0; k < TH; ++k) {
            smemC[(k << 9) + st] = s;
            s += pa[(size_t)k * WW] - pb[(size_t)k * WW];
        }
    } else {
        #pragma unroll
        for (int k = 0; k < TH; ++k) {
            smemC[(k << 9) + st] = s;
            int add = h0 + k + RH + 1;
            int sb  = h0 + k - RH;
            float a = (add < HH) ? xp[(size_t)add * WW] : 0.f;
            float b = (sb >= 0)  ? xp[(size_t)sb * WW]  : 0.f;
            s += a - b;
        }
    }
    __syncthreads();

    // ---- phase B: per-warp row prefix scan in registers ---------------------
    const unsigned FULL = 0xffffffffu;
    float* __restrict__ row = smemC + (wrp << 9);

    float p[16];
    #pragma unroll
    for (int c = 0; c < 4; ++c) {
        int u = (lane << 2) + c;
        int pu = u ^ ((u >> 3) & 7);
        float4 v = *reinterpret_cast<const float4*>(row + (pu << 2));
        p[c * 4 + 0] = v.x; p[c * 4 + 1] = v.y; p[c * 4 + 2] = v.z; p[c * 4 + 3] = v.w;
    }
    #pragma unroll
    for (int j = 1; j < 16; ++j) p[j] += p[j - 1];
    float tot = p[15];
    float inc = tot;
    #pragma unroll
    for (int off = 1; off < 32; off <<= 1) {
        float u = __shfl_up_sync(FULL, inc, off);
        if (lane >= off) inc += u;
    }
    float excl = inc - tot;
    #pragma unroll
    for (int j = 0; j < 16; ++j) p[j] += excl;
    #pragma unroll
    for (int c = 0; c < 4; ++c) {
        int u = (lane << 2) + c;
        int pu = u ^ ((u >> 3) & 7);
        *reinterpret_cast<float4*>(row + (pu << 2)) =
            make_float4(p[c * 4 + 0], p[c * 4 + 1], p[c * 4 + 2], p[c * 4 + 3]);
    }
    __syncwarp();  // only this warp touches this row

    // ---- epilogue: window diff + normalize (coalesced) ----------------------
    const float inv_cnt = 1.0f / (float)(KH * KW);
    const float inv_std = 0.2f;  // 1/5
    const size_t rbase = gbase + (size_t)(h0 + wrp) * WW;
    #pragma unroll
    for (int i = 0; i < 16; ++i) {
        int w = lane + (i << 5);
        int hiI = w + RW; if (hiI > WW - 1) hiI = WW - 1;
        int loI = w - RW - 1;
        float hiv = row[swz(hiI)];
        float lov = (loI >= 0) ? row[swz(loI)] : 0.0f;
        float winsum = hiv - lov;
        size_t o = rbase + w;
        float r = (x[o] - winsum * inv_cnt) * inv_std;
        __stcs(&out[o], r);   // streaming store: don't thrash L2 (keep x hot)
    }
}

extern "C" void kernel_launch(void* const* d_in, const int* in_sizes, int n_in,
                              void* d_out, int out_size) {
    const float* x = (const float*)d_in[0];
    float* out = (float*)d_out;

    s8_kernel<<<NB * NG, 512>>>(x);
    sliding_mean_fused<<<NB * (HH / TH), 512>>>(x, out);
}